// round 14
// baseline (speedup 1.0000x reference)
#include <cuda_runtime.h>
#include <math.h>
#include <stdint.h>

// R14 = R13 (cluster-2 K-split + st.async partial exchange) with:
//  - enc1/enc2 dual-batch accumulators (each weight LDS'd once, 2 FMAs)
//  - raster factored 2sy x 2sx: crossing per-sy (exact predicates), distance
//    deltas v+tx/v+ty/v+tx+ty.

#define TPB 832
#define NC 512
#define NGATE 800
#define CLUSTER 2
#define NSTAGES 3
#define SLOT_BYTES 57344
#define SLOT_FLOATS 14336
#define NT 29
#define HALFC 14.0f
#define SCALEC 12.0f

#define OUT_R  0
#define OUT_MU (128*784)
#define OUT_LV (OUT_MU + 128*64)
#define OUT_CP (OUT_LV + 128*64)
#define OUT_W  (OUT_CP + 128*64)
#define OUT_A  (OUT_W + 128*2)

#define XB_H1 0
#define XB_H2 1
#define XB_MU 2
#define XB_LV 3
#define XB_D1 4
#define XB_D2 5
#define XB_CP 6
#define XB_WA 7
#define XB_R1 8
#define XB_R2 9
#define RO_H1 0
#define RO_H2 512
#define RO_MU 1024
#define RO_LV 1152
#define RO_D1 1280
#define RO_D2 2304
#define RO_CP 3328
#define RO_WA 3392
#define RO_R1 3408
#define RO_R2 4432
#define RTOT  4544

struct WPtrs { const float *ew1,*ew2,*muw,*lvw,*dw1,*dw2,*cpw,*wdw,*alw,*rw1,*rw2; };

__device__ __forceinline__ uint32_t smem_u32(const void* p){ return (uint32_t)__cvta_generic_to_shared(p); }
__device__ __forceinline__ void mbar_init(uint32_t a, uint32_t c){
    asm volatile("mbarrier.init.shared.b64 [%0], %1;" :: "r"(a),"r"(c) : "memory"); }
__device__ __forceinline__ void mbar_wait(uint32_t a, uint32_t par){
    asm volatile("{\n\t.reg .pred P;\nW_%=:\n\t"
        "mbarrier.try_wait.parity.acquire.cta.shared::cta.b64 P, [%0], %1, 0x989680;\n\t"
        "@P bra.uni D_%=;\n\tbra.uni W_%=;\nD_%=:\n\t}" :: "r"(a),"r"(par) : "memory"); }
__device__ __forceinline__ void mbar_expect_tx(uint32_t a, uint32_t b){
    asm volatile("mbarrier.arrive.expect_tx.shared.b64 _, [%0], %1;" :: "r"(a),"r"(b) : "memory"); }
__device__ __forceinline__ void mbar_arrive_local(uint32_t a){
    asm volatile("mbarrier.arrive.shared.b64 _, [%0];" :: "r"(a) : "memory"); }
__device__ __forceinline__ void cluster_sync_all(){
    asm volatile("barrier.cluster.arrive.aligned;" ::: "memory");
    asm volatile("barrier.cluster.wait.aligned;" ::: "memory"); }
__device__ __forceinline__ void bulk_cta(uint32_t d, const void* s, uint32_t b, uint32_t m){
    asm volatile("cp.async.bulk.shared::cluster.global.mbarrier::complete_tx::bytes "
        "[%0], [%1], %2, [%3];" :: "r"(d),"l"(s),"r"(b),"r"(m) : "memory"); }
__device__ __forceinline__ void st_peer(uint32_t laddr, uint32_t lbar, float v, uint32_t peer){
    uint32_t ra, rb, vu = __float_as_uint(v);
    asm volatile("mapa.shared::cluster.u32 %0, %1, %2;" : "=r"(ra) : "r"(laddr),"r"(peer));
    asm volatile("mapa.shared::cluster.u32 %0, %1, %2;" : "=r"(rb) : "r"(lbar),"r"(peer));
    asm volatile("st.async.weak.shared::cluster.mbarrier::complete_tx::bytes.b32 [%0], %1, [%2];"
                 :: "r"(ra),"r"(vu),"r"(rb) : "memory");
}

__device__ __forceinline__ float seluf(float x){
    const float sc = 1.0507009873554805f, al = 1.6732632423543772f;
    return x > 0.0f ? sc*x : sc*al*(expf(x)-1.0f); }
__device__ __forceinline__ float lrelu(float x){ return x >= 0.0f ? x : 0.2f*x; }
__device__ __forceinline__ float sigm(float x){ return 1.0f/(1.0f+expf(-x)); }

// 29 contiguous row-block half tiles (identical to R13)
__device__ __forceinline__ int tile_segs(int n, const WPtrs& p, uint32_t rank,
                                         const char* srcs[2], uint32_t szs[2]) {
    if (n < 7)  { srcs[0]=(const char*)(p.ew1 + (rank*392 + n*56)*256); szs[0]=57344; return 1; }
    n -= 7;
    if (n < 3)  { int off = n*56, rows = (n<2)?56:16;
                  srcs[0]=(const char*)(p.ew2 + (rank*128 + off)*256); szs[0]=rows*1024; return 1; }
    n -= 3;
    if (n == 0) { srcs[0]=(const char*)(p.muw + rank*128*64); szs[0]=32768; return 1; } n--;
    if (n == 0) { srcs[0]=(const char*)(p.lvw + rank*128*64); szs[0]=32768; return 1; } n--;
    if (n < 2)  { srcs[0]=(const char*)(p.dw1 + (rank*32 + n*16)*512); szs[0]=32768; return 1; }
    n -= 2;
    if (n < 10) { int rows = (n<9)?28:4;
                  srcs[0]=(const char*)(p.dw2 + (rank*256 + n*28)*512); szs[0]=rows*2048; return 1; }
    n -= 10;
    if (n == 0) { srcs[0]=(const char*)(p.cpw + rank*256*28); szs[0]=28672; return 1; } n--;
    if (n == 0) { srcs[0]=(const char*)(p.wdw + rank*256*2); szs[0]=2048;
                  srcs[1]=(const char*)(p.alw + rank*256*2); szs[1]=2048; return 2; } n--;
    if (n < 2)  { int off = n*28, rows = (n<1)?28:18;
                  srcs[0]=(const char*)(p.rw1 + (rank*46 + off)*512); szs[0]=rows*2048; return 1; }
    n -= 2;
    srcs[0]=(const char*)(p.rw2 + rank*256*52); szs[0]=53248; return 1;
}

__device__ __forceinline__ void produce(int j, uint32_t bar_base, uint32_t ring_base,
                                        const WPtrs& p, uint32_t rank){
    const int s = j % NSTAGES;
    mbar_wait(bar_base + s*16 + 8, 1u ^ ((uint32_t)(j/NSTAGES) & 1u));
    const char* srcs[2]; uint32_t szs[2];
    int ns = tile_segs(j, p, rank, srcs, szs);
    uint32_t total = szs[0] + ((ns > 1) ? szs[1] : 0u);
    const uint32_t full = bar_base + s*16;
    mbar_expect_tx(full, total);
    uint32_t dst = ring_base + s*SLOT_BYTES;
    for (int k = 0; k < ns; k++){ bulk_cta(dst, srcs[k], szs[k], full); dst += szs[k]; }
}

#define CONS_SYNC() asm volatile("bar.sync 1, %0;" :: "n"(NC) : "memory")
#define GATE_SYNC() asm volatile("bar.sync 2, %0;" :: "n"(NGATE) : "memory")
#define TILE_BEGIN() do { \
        mbar_wait(bar_base + (tn % NSTAGES)*16, (uint32_t)(tn/NSTAGES) & 1u); \
        ws = wb + (tn % NSTAGES)*SLOT_FLOATS; } while (0)
#define TILE_END() do { __syncwarp(); \
        if ((tid & 31) == 0) mbar_arrive_local(bar_base + (tn % NSTAGES)*16 + 8); \
        tn++; } while (0)
#define HSUM(own, rcv) ((rank == 0) ? ((own) + (rcv)) : ((rcv) + (own)))

__global__ void __launch_bounds__(TPB, 1) __cluster_dims__(CLUSTER, 1, 1)
fused_kernel(
    const float* __restrict__ x,   const float* __restrict__ eps,
    const float* __restrict__ ew1, const float* __restrict__ eb1,
    const float* __restrict__ ew2, const float* __restrict__ eb2,
    const float* __restrict__ muw, const float* __restrict__ mub,
    const float* __restrict__ lvw, const float* __restrict__ lvb,
    const float* __restrict__ dw1, const float* __restrict__ db1,
    const float* __restrict__ dw2, const float* __restrict__ db2,
    const float* __restrict__ cpw, const float* __restrict__ cpb,
    const float* __restrict__ rw1, const float* __restrict__ rb1,
    const float* __restrict__ rw2w,const float* __restrict__ rb2,
    const float* __restrict__ wdw, const float* __restrict__ wdb,
    const float* __restrict__ alw, const float* __restrict__ alb,
    float* __restrict__ out)
{
    extern __shared__ float wb[];
    const int b = blockIdx.x, tid = threadIdx.x;
    const int bp = b & ~1;

    __shared__ alignas(16) unsigned long long mbars[NSTAGES*2 + 10];
    __shared__ alignas(16) float x2[1568];
    __shared__ float h1[512], h2[512];
    __shared__ float hin[184];
    __shared__ float d1[1024], d2[1024], r1[1024];
    __shared__ float pts[52];
    __shared__ float recvb[RTOT];
    __shared__ float qx[64], qy[64], wa[4];
    __shared__ float red[512], red2[512];
    __shared__ alignas(16) float4 pt4[64];

    WPtrs wp; wp.ew1=ew1; wp.ew2=ew2; wp.muw=muw; wp.lvw=lvw; wp.dw1=dw1;
    wp.dw2=dw2; wp.cpw=cpw; wp.wdw=wdw; wp.alw=alw; wp.rw1=rw1; wp.rw2=rw2w;

    const uint32_t bar_base = smem_u32(mbars);
    const uint32_t xb       = bar_base + NSTAGES*16;
    const uint32_t rcv      = smem_u32(recvb);
    uint32_t rank; asm("mov.u32 %0, %%cluster_ctarank;" : "=r"(rank));
    const uint32_t peer = rank ^ 1u;

    if (tid == 0){
        #pragma unroll
        for (int s = 0; s < NSTAGES; s++){
            mbar_init(bar_base + s*16, 1);
            mbar_init(bar_base + s*16 + 8, 16);
        }
        const uint32_t xbytes[10] = {2048,2048,512,512,4096,4096,224,32,4096,416};
        #pragma unroll
        for (int k = 0; k < 10; k++){
            mbar_init(xb + k*8, 1);
            mbar_expect_tx(xb + k*8, xbytes[k]);
        }
    }
    __syncthreads();
    cluster_sync_all();

    if (tid >= NGATE){
        if (tid == NGATE)
            for (int j = 0; j < NT; j++) produce(j, bar_base, smem_u32(wb), wp, rank);
    } else {
        if (tid < NC){
            for (int i = tid; i < 1568; i += NC) x2[i] = x[bp*784 + i];
            CONS_SYNC();

            int tn = 0; float* ws;

            // ===== enc1: 7 tiles x 56 rows; thread=(kg2,c), dual-batch =====
            {
                const int kg = tid >> 8, c = tid & 255;
                float a0 = 0.0f, a1 = 0.0f;
                for (int t = 0; t < 7; t++){
                    TILE_BEGIN();
                    const int rb = kg*28;
                    const float* x0 = x2 + rank*392 + t*56 + rb;
                    const float* x1p = x2 + 784 + rank*392 + t*56 + rb;
                    const float* wq = ws + rb*256 + c;
                    #pragma unroll 7
                    for (int r = 0; r < 28; r++){
                        const float w = wq[r*256];
                        a0 = fmaf(x0[r], w, a0); a1 = fmaf(x1p[r], w, a1);
                    }
                    TILE_END();
                }
                red[tid] = a0; red2[tid] = a1;
            }
            CONS_SYNC();
            {
                float p0 = 0.0f, p1 = 0.0f;
                if (tid < 256){
                    p0 = red[tid] + red[256 + tid];
                    p1 = red2[tid] + red2[256 + tid];
                    st_peer(rcv + (RO_H1 + tid)*4, xb + XB_H1*8, p0, peer);
                    st_peer(rcv + (RO_H1 + 256 + tid)*4, xb + XB_H1*8, p1, peer);
                }
                mbar_wait(xb + XB_H1*8, 0);
                if (tid < 256){
                    h1[tid]       = lrelu(eb1[tid] + HSUM(p0, recvb[RO_H1 + tid]));
                    h1[256 + tid] = lrelu(eb1[tid] + HSUM(p1, recvb[RO_H1 + 256 + tid]));
                }
            }
            CONS_SYNC();

            // ===== enc2: 3 tiles {56,56,16}; thread=(kg2,c), dual-batch =====
            {
                const int kg = tid >> 8, c = tid & 255;
                float a0 = 0.0f, a1 = 0.0f;
                for (int t = 0; t < 3; t++){
                    TILE_BEGIN();
                    const int half = (t < 2) ? 28 : 8;
                    const int rb = kg*half;
                    const float* h0 = h1 + rank*128 + t*56 + rb;
                    const float* h1p = h1 + 256 + rank*128 + t*56 + rb;
                    const float* wq = ws + rb*256 + c;
                    #pragma unroll 7
                    for (int r = 0; r < half; r++){
                        const float w = wq[r*256];
                        a0 = fmaf(h0[r], w, a0); a1 = fmaf(h1p[r], w, a1);
                    }
                    TILE_END();
                }
                red[tid] = a0; red2[tid] = a1;
            }
            CONS_SYNC();
            {
                float p0 = 0.0f, p1 = 0.0f;
                if (tid < 256){
                    p0 = red[tid] + red[256 + tid];
                    p1 = red2[tid] + red2[256 + tid];
                    st_peer(rcv + (RO_H2 + tid)*4, xb + XB_H2*8, p0, peer);
                    st_peer(rcv + (RO_H2 + 256 + tid)*4, xb + XB_H2*8, p1, peer);
                }
                mbar_wait(xb + XB_H2*8, 0);
                if (tid < 256){
                    h2[tid]       = lrelu(eb2[tid] + HSUM(p0, recvb[RO_H2 + tid]));
                    h2[256 + tid] = lrelu(eb2[tid] + HSUM(p1, recvb[RO_H2 + 256 + tid]));
                }
            }
            CONS_SYNC();

            float mu_tot = 0.0f;

            // ===== mu: 1 tile 128x64 =====
            {
                float a = 0.0f;
                const int bb = tid >> 6, l = tid & 63;
                TILE_BEGIN();
                if (tid < 128){
                    const float* hp = h2 + bb*256 + rank*128;
                    #pragma unroll 8
                    for (int r = 0; r < 128; r++) a = fmaf(hp[r], ws[r*64 + l], a);
                }
                TILE_END();
                if (tid < 128) st_peer(rcv + (RO_MU + tid)*4, xb + XB_MU*8, a, peer);
                mbar_wait(xb + XB_MU*8, 0);
                if (tid < 128) mu_tot = mub[l] + HSUM(a, recvb[RO_MU + tid]);
            }

            // ===== logvar + z =====
            {
                float a = 0.0f;
                const int bb = tid >> 6, l = tid & 63;
                TILE_BEGIN();
                if (tid < 128){
                    const float* hp = h2 + bb*256 + rank*128;
                    #pragma unroll 8
                    for (int r = 0; r < 128; r++) a = fmaf(hp[r], ws[r*64 + l], a);
                }
                TILE_END();
                if (tid < 128) st_peer(rcv + (RO_LV + tid)*4, xb + XB_LV*8, a, peer);
                mbar_wait(xb + XB_LV*8, 0);
                if (tid < 128){
                    float lvt = lvb[l] + HSUM(a, recvb[RO_LV + tid]);
                    if (bb == (int)rank){
                        out[OUT_MU + b*64 + l] = mu_tot;
                        out[OUT_LV + b*64 + l] = lvt;
                    }
                    hin[bb*92 + l] = mu_tot + eps[(bp + bb)*64 + l]*expf(0.5f*lvt);
                }
            }
            CONS_SYNC();

            // ===== dec1: 2 tiles x 16 rows; thread=c, dual bb =====
            {
                const int c = tid;
                float a0 = 0.0f, a1 = 0.0f;
                for (int t = 0; t < 2; t++){
                    TILE_BEGIN();
                    const float* h0 = hin + rank*32 + t*16;
                    const float* h1p = hin + 92 + rank*32 + t*16;
                    #pragma unroll 8
                    for (int r = 0; r < 16; r++){
                        const float w = ws[r*512 + c];
                        a0 = fmaf(h0[r], w, a0); a1 = fmaf(h1p[r], w, a1);
                    }
                    TILE_END();
                }
                st_peer(rcv + (RO_D1 + c)*4, xb + XB_D1*8, a0, peer);
                st_peer(rcv + (RO_D1 + 512 + c)*4, xb + XB_D1*8, a1, peer);
                mbar_wait(xb + XB_D1*8, 0);
                d1[c]       = seluf(db1[c] + HSUM(a0, recvb[RO_D1 + c]));
                d1[512 + c] = seluf(db1[c] + HSUM(a1, recvb[RO_D1 + 512 + c]));
            }
            CONS_SYNC();

            // ===== dec2: 10 tiles {28x9,4}; thread=c, dual bb =====
            {
                const int c = tid;
                float a0 = 0.0f, a1 = 0.0f;
                for (int t = 0; t < 10; t++){
                    TILE_BEGIN();
                    const int rows = (t < 9) ? 28 : 4;
                    const float* p0 = d1 + rank*256 + t*28;
                    const float* p1 = d1 + 512 + rank*256 + t*28;
                    #pragma unroll 7
                    for (int r = 0; r < rows; r++){
                        const float w = ws[r*512 + c];
                        a0 = fmaf(p0[r], w, a0); a1 = fmaf(p1[r], w, a1);
                    }
                    TILE_END();
                }
                st_peer(rcv + (RO_D2 + c)*4, xb + XB_D2*8, a0, peer);
                st_peer(rcv + (RO_D2 + 512 + c)*4, xb + XB_D2*8, a1, peer);
                mbar_wait(xb + XB_D2*8, 0);
                d2[c]       = seluf(db2[c] + HSUM(a0, recvb[RO_D2 + c]));
                d2[512 + c] = seluf(db2[c] + HSUM(a1, recvb[RO_D2 + 512 + c]));
            }
            CONS_SYNC();

            // ===== coarse cp: 1 tile 256x28 =====
            {
                float a = 0.0f;
                const int bb = tid >> 5, l = tid & 31;
                TILE_BEGIN();
                if (tid < 64 && l < 28){
                    const float* dp = d2 + bb*512 + rank*256;
                    #pragma unroll 8
                    for (int r = 0; r < 256; r++) a = fmaf(dp[r], ws[r*28 + l], a);
                }
                TILE_END();
                if (tid < 64 && l < 28)
                    st_peer(rcv + (RO_CP + bb*28 + l)*4, xb + XB_CP*8, a, peer);
                mbar_wait(xb + XB_CP*8, 0);
                if (tid < 64 && l < 28)
                    hin[bb*92 + 64 + l] = tanhf(cpb[l] + HSUM(a, recvb[RO_CP + bb*28 + l]));
            }
            CONS_SYNC();

            // ===== widths+alphas =====
            {
                float a = 0.0f;
                const int bb = tid >> 2, k = tid & 3;
                TILE_BEGIN();
                if (tid < 8){
                    const float* dp = d2 + bb*512 + rank*256;
                    const float* wq = ws + ((k < 2) ? 0 : 512) + (k & 1);
                    #pragma unroll 8
                    for (int r = 0; r < 256; r++) a = fmaf(dp[r], wq[r*2], a);
                }
                TILE_END();
                if (tid < 8) st_peer(rcv + (RO_WA + tid)*4, xb + XB_WA*8, a, peer);
                mbar_wait(xb + XB_WA*8, 0);
                if (tid < 8 && bb == (int)rank){
                    float s = HSUM(a, recvb[RO_WA + tid]);
                    if (k < 2){
                        float wv = sigm(wdb[k] + s)*2.0f + 1.0f;
                        wa[k] = wv; out[OUT_W + b*2 + k] = wv;
                    } else {
                        float av = sigm(alb[k & 1] + s);
                        wa[k] = av; out[OUT_A + b*2 + (k & 1)] = av;
                    }
                }
            }
            CONS_SYNC();

            // ===== refine1: 2 tiles {28,18}; thread=c, dual bb =====
            {
                const int c = tid;
                float a0 = 0.0f, a1 = 0.0f;
                for (int t = 0; t < 2; t++){
                    TILE_BEGIN();
                    const int rows = (t < 1) ? 28 : 18;
                    const float* p0 = hin + rank*46 + t*28;
                    const float* p1 = hin + 92 + rank*46 + t*28;
                    #pragma unroll 7
                    for (int r = 0; r < rows; r++){
                        const float w = ws[r*512 + c];
                        a0 = fmaf(p0[r], w, a0); a1 = fmaf(p1[r], w, a1);
                    }
                    TILE_END();
                }
                st_peer(rcv + (RO_R1 + c)*4, xb + XB_R1*8, a0, peer);
                st_peer(rcv + (RO_R1 + 512 + c)*4, xb + XB_R1*8, a1, peer);
                mbar_wait(xb + XB_R1*8, 0);
                r1[c]       = seluf(rb1[c] + HSUM(a0, recvb[RO_R1 + c]));
                r1[512 + c] = seluf(rb1[c] + HSUM(a1, recvb[RO_R1 + 512 + c]));
            }
            CONS_SYNC();

            // ===== refine2: 1 tile 256x52 =====
            {
                float a = 0.0f;
                const int bb = tid >> 6, l = tid & 63;
                TILE_BEGIN();
                if (tid < 128 && l < 52){
                    const float* rp = r1 + bb*512 + rank*256;
                    #pragma unroll 8
                    for (int r = 0; r < 256; r++) a = fmaf(rp[r], ws[r*52 + l], a);
                }
                TILE_END();
                if (tid < 128 && l < 52)
                    st_peer(rcv + (RO_R2 + bb*52 + l)*4, xb + XB_R2*8, a, peer);
                mbar_wait(xb + XB_R2*8, 0);
                if (tid < 128 && l < 52 && bb == (int)rank)
                    pts[l] = tanhf(rb2[l] + HSUM(a, recvb[RO_R2 + bb*52 + l]))*SCALEC + HALFC;
            }
            CONS_SYNC();

            // ===== control points out + bezier eval =====
            if (tid < 64){
                const int p = tid >> 5, rem = tid & 31;
                { int s = rem >> 3, k = (rem >> 1) & 3, d = rem & 1;
                  out[OUT_CP + b*64 + tid] = pts[p*26 + (3*s + k)*2 + d]; }
                const int ss = rem >> 3, ti = rem & 7;
                float t = (float)ti/7.0f, mt = 1.0f - t;
                float c0 = mt*mt*mt, c1 = 3.0f*mt*mt*t, c2 = 3.0f*mt*t*t, c3 = t*t*t;
                int base = p*26 + (3*ss)*2;
                float X = c0*pts[base+0] + c1*pts[base+2] + c2*pts[base+4] + c3*pts[base+6];
                float Y = c0*pts[base+1] + c1*pts[base+3] + c2*pts[base+5] + c3*pts[base+7];
                qx[tid] = X; qy[tid] = Y;
            }
            CONS_SYNC();
            if (tid < 64){
                const int p = tid >> 5, m = tid & 31;
                float X = qx[tid], Y = qy[tid];
                float y1 = qy[p*32 + ((m+1) & 31)];
                float si = __fdiv_rn(1.0f, (y1 - Y) + 1e-8f);
                pt4[tid] = make_float4(X, Y, X*X + Y*Y, si);
            }
        }

        GATE_SYNC();

        // ===== rasterizer: 1 px/thread, 2sy x 2sx factored =====
        if (tid < 784){
            const int pi = tid/28, pj = tid - pi*28;
            const float sy0 = (float)pi + 0.25f, sy1 = (float)pi + 0.75f;
            const float sx0 = (float)pj + 0.25f, sx1 = (float)pj + 0.75f;
            const float sxq = sx0 + 0.25f, syq = sy0 + 0.25f;
            const float nx0 = -2.0f*sx0, ny0 = -2.0f*sy0;
            const float ssn00 = sx0*sx0 + sy0*sy0;
            float val0 = 1.0f, val1 = 1.0f, val2 = 1.0f, val3 = 1.0f;
            #pragma unroll
            for (int p = 0; p < 2; p++){
                const int base = p*32;
                float m00 = 3.402823e38f, m10 = m00, m01 = m00, m11 = m00;
                int n00 = 0, n10 = 0, n01 = 0, n11 = 0;
                float4 e = pt4[base];
                bool c0a = e.y > sy0, c0b = e.y > sy1;
                #pragma unroll 8
                for (int m = 0; m < 32; m++){
                    const float4 e1 = pt4[base + ((m+1) & 31)];
                    const float dx = e1.x - e.x;
                    // distance: v00 exact for sub0, deltas for others
                    const float v00 = fmaf(nx0, e.x, fmaf(ny0, e.y, e.z + ssn00));
                    const float tx = sxq - e.x, ty = syq - e.y;
                    m00 = fminf(m00, v00);
                    m10 = fminf(m10, v00 + tx);
                    const float v01 = v00 + ty;
                    m01 = fminf(m01, v01);
                    m11 = fminf(m11, v01 + tx);
                    // crossing per sy (predicates identical to reference formulas)
                    const bool c1a = e1.y > sy0;
                    const bool c1b = e1.y > sy1;
                    const float xa = fmaf((sy0 - e.y)*e.w, dx, e.x);
                    const float xbv = fmaf((sy1 - e.y)*e.w, dx, e.x);
                    const bool ka = (c0a != c1a), kb = (c0b != c1b);
                    n00 += (int)(ka && (sx0 < xa));
                    n10 += (int)(ka && (sx1 < xa));
                    n01 += (int)(kb && (sx0 < xbv));
                    n11 += (int)(kb && (sx1 < xbv));
                    c0a = c1a; c0b = c1b; e = e1;
                }
                const float sw = fmaf(wa[p], 0.5f, 0.5f);
                const float al2 = wa[2+p];
                float d, st, cv;
                d = sqrtf(fmaxf(m00, 0.0f)); st = fminf(fmaxf(sw - d, 0.0f), 1.0f);
                cv = fmaxf((float)(n00 & 1), st); val0 *= 1.0f - al2*cv;
                d = sqrtf(fmaxf(m10, 0.0f)); st = fminf(fmaxf(sw - d, 0.0f), 1.0f);
                cv = fmaxf((float)(n10 & 1), st); val1 *= 1.0f - al2*cv;
                d = sqrtf(fmaxf(m01, 0.0f)); st = fminf(fmaxf(sw - d, 0.0f), 1.0f);
                cv = fmaxf((float)(n01 & 1), st); val2 *= 1.0f - al2*cv;
                d = sqrtf(fmaxf(m11, 0.0f)); st = fminf(fmaxf(sw - d, 0.0f), 1.0f);
                cv = fmaxf((float)(n11 & 1), st); val3 *= 1.0f - al2*cv;
            }
            const float acc = (val0 + val1) + (val2 + val3);
            out[OUT_R + b*784 + tid] = 1.0f - 0.25f*acc;
        }
    }

    cluster_sync_all();
}

extern "C" void kernel_launch(void* const* d_in, const int* in_sizes, int n_in,
                              void* d_out, int out_size)
{
    const float* x   = (const float*)d_in[0];
    const float* eps = (const float*)d_in[1];
    const float* ew1 = (const float*)d_in[2];
    const float* eb1 = (const float*)d_in[3];
    const float* ew2 = (const float*)d_in[4];
    const float* eb2 = (const float*)d_in[5];
    const float* muw = (const float*)d_in[6];
    const float* mub = (const float*)d_in[7];
    const float* lvw = (const float*)d_in[8];
    const float* lvb = (const float*)d_in[9];
    const float* dw1 = (const float*)d_in[10];
    const float* db1 = (const float*)d_in[11];
    const float* dw2 = (const float*)d_in[12];
    const float* db2 = (const float*)d_in[13];
    const float* cpw = (const float*)d_in[14];
    const float* cpb = (const float*)d_in[15];
    const float* rw1 = (const float*)d_in[16];
    const float* rb1 = (const float*)d_in[17];
    const float* rw2 = (const float*)d_in[18];
    const float* rb2 = (const float*)d_in[19];
    const float* wdw = (const float*)d_in[20];
    const float* wdb = (const float*)d_in[21];
    const float* alw = (const float*)d_in[22];
    const float* alb = (const float*)d_in[23];
    float* out = (float*)d_out;

    const int dyn = NSTAGES*SLOT_BYTES;
    cudaFuncSetAttribute(fused_kernel, cudaFuncAttributeMaxDynamicSharedMemorySize, dyn);
    fused_kernel<<<128, TPB, dyn>>>(x, eps, ew1, eb1, ew2, eb2, muw, mub, lvw, lvb,
                                    dw1, db1, dw2, db2, cpw, cpb, rw1, rb1, rw2, rb2,
                                    wdw, wdb, alw, alb, out);
}

// round 15
// speedup vs baseline: 1.5791x; 1.5791x over previous
#include <cuda_runtime.h>
#include <math.h>
#include <stdint.h>

// R15 = R10 (best: 42.8us) with micro-hoists in the raster epilogue.
// Cluster-4 multicast weight streaming, warp-specialized producer, float4 big
// layers, 832 thr: tid<512 MLP, warps 16-24 raster extras, tid 800 producer.

#define BATCH 128
#define TPB 832
#define NC 512
#define NGATE 800
#define CLUSTER 4
#define NSTAGES 3
#define STAGE_FLOATS 16384
#define STAGE_BYTES  65536
#define NT 44
#define HALFC 14.0f
#define SCALEC 12.0f

#define OUT_R  0
#define OUT_MU (BATCH*784)
#define OUT_LV (OUT_MU + BATCH*64)
#define OUT_CP (OUT_LV + BATCH*64)
#define OUT_W  (OUT_CP + BATCH*64)
#define OUT_A  (OUT_W + BATCH*2)

struct WPtrs {
    const float *ew1, *ew2, *muw, *lvw, *dw1, *dw2, *cpw, *wdw, *alw, *rw1, *rw2;
};

__device__ __forceinline__ uint32_t smem_u32(const void* p) {
    return (uint32_t)__cvta_generic_to_shared(p);
}
__device__ __forceinline__ void mbar_init(uint32_t addr, uint32_t count) {
    asm volatile("mbarrier.init.shared.b64 [%0], %1;" :: "r"(addr), "r"(count) : "memory");
}
__device__ __forceinline__ void mbar_wait(uint32_t addr, uint32_t parity) {
    asm volatile(
        "{\n\t.reg .pred P;\n"
        "W_%=:\n\t"
        "mbarrier.try_wait.parity.acquire.cta.shared::cta.b64 P, [%0], %1, 0x989680;\n\t"
        "@P bra.uni D_%=;\n\t"
        "bra.uni W_%=;\n"
        "D_%=:\n\t}"
        :: "r"(addr), "r"(parity) : "memory");
}
__device__ __forceinline__ void mbar_expect_tx(uint32_t addr, uint32_t bytes) {
    asm volatile("mbarrier.arrive.expect_tx.shared.b64 _, [%0], %1;"
                 :: "r"(addr), "r"(bytes) : "memory");
}
__device__ __forceinline__ void mbar_arrive_rank(uint32_t addr, uint32_t rank) {
    asm volatile(
        "{\n\t.reg .b32 ra;\n\t"
        "mapa.shared::cluster.u32 ra, %0, %1;\n\t"
        "mbarrier.arrive.shared::cluster.b64 _, [ra];\n\t}"
        :: "r"(addr), "r"(rank) : "memory");
}
__device__ __forceinline__ void cluster_sync_all() {
    asm volatile("barrier.cluster.arrive.aligned;" ::: "memory");
    asm volatile("barrier.cluster.wait.aligned;" ::: "memory");
}
__device__ __forceinline__ void bulk_mc(uint32_t dst, const void* src, uint32_t bytes,
                                        uint32_t mbar, uint16_t mask) {
    asm volatile(
        "cp.async.bulk.shared::cluster.global.mbarrier::complete_tx::bytes.multicast::cluster "
        "[%0], [%1], %2, [%3], %4;"
        :: "r"(dst), "l"(src), "r"(bytes), "r"(mbar), "h"(mask) : "memory");
}

__device__ __forceinline__ float seluf(float x) {
    const float sc = 1.0507009873554805f;
    const float al = 1.6732632423543772f;
    return x > 0.0f ? sc * x : sc * al * (expf(x) - 1.0f);
}
__device__ __forceinline__ float lrelu(float x) { return x >= 0.0f ? x : 0.2f * x; }
__device__ __forceinline__ float sigm(float x)  { return 1.0f / (1.0f + expf(-x)); }

// Tile table (44 tiles) — identical to R10.
__device__ __forceinline__ int tile_segs(int n, const WPtrs& p,
                                         const char* srcs[2], uint32_t szs[2]) {
    if (n < 13) { int r0 = n * 64; int rows = (r0 + 64 <= 784) ? 64 : (784 - r0);
                  srcs[0] = (const char*)(p.ew1 + r0 * 256); szs[0] = rows * 1024; return 1; }
    n -= 13;
    if (n < 4)  { srcs[0] = (const char*)(p.ew2 + n * 64 * 256); szs[0] = 65536; return 1; }
    n -= 4;
    if (n == 0) { srcs[0] = (const char*)p.muw; szs[0] = 65536; return 1; } n--;
    if (n == 0) { srcs[0] = (const char*)p.lvw; szs[0] = 65536; return 1; } n--;
    if (n < 2)  { srcs[0] = (const char*)(p.dw1 + n * 32 * 512); szs[0] = 65536; return 1; }
    n -= 2;
    if (n < 16) { srcs[0] = (const char*)(p.dw2 + n * 32 * 512); szs[0] = 65536; return 1; }
    n -= 16;
    if (n == 0) { srcs[0] = (const char*)p.cpw; szs[0] = 57344; return 1; } n--;
    if (n == 0) { srcs[0] = (const char*)p.wdw; szs[0] = 4096;
                  srcs[1] = (const char*)p.alw; szs[1] = 4096; return 2; } n--;
    if (n < 3)  { int r0 = n * 32; int rows = (r0 + 32 <= 92) ? 32 : (92 - r0);
                  srcs[0] = (const char*)(p.rw1 + r0 * 512); szs[0] = rows * 2048; return 1; }
    n -= 3;
    srcs[0] = (const char*)(p.rw2 + n * 256 * 52); szs[0] = 53248; return 1;
}

__device__ __forceinline__ void produce(int j, uint32_t bar_base, uint32_t ring_base,
                                        const WPtrs& p, uint32_t rank) {
    const int s = j % NSTAGES;
    mbar_wait(bar_base + s * 16 + 8, 1u ^ ((uint32_t)(j / NSTAGES) & 1u));
    const char* srcs[2]; uint32_t szs[2];
    int ns = tile_segs(j, p, srcs, szs);
    uint32_t total = szs[0] + ((ns > 1) ? szs[1] : 0u);
    const uint32_t full = bar_base + s * 16;
    mbar_expect_tx(full, total);
    uint32_t dst = ring_base + s * STAGE_BYTES;
    for (int k = 0; k < ns; k++) {
        uint32_t slice = szs[k] >> 2;
        bulk_mc(dst + rank * slice, srcs[k] + rank * slice, slice, full, 0xF);
        dst += szs[k];
    }
}

#define CONS_SYNC() asm volatile("bar.sync 1, %0;" :: "n"(NC) : "memory")
#define GATE_SYNC() asm volatile("bar.sync 2, %0;" :: "n"(NGATE) : "memory")

#define TILE_BEGIN() do { \
        mbar_wait(bar_base + (tn % NSTAGES) * 16, (uint32_t)(tn / NSTAGES) & 1u); \
        ws = wb + (tn % NSTAGES) * STAGE_FLOATS; } while (0)

#define TILE_END() do { __syncwarp(); \
        if ((tid & 31) == 0) { uint32_t e = bar_base + (tn % NSTAGES) * 16 + 8; \
            mbar_arrive_rank(e, 0); mbar_arrive_rank(e, 1); \
            mbar_arrive_rank(e, 2); mbar_arrive_rank(e, 3); } \
        tn++; } while (0)

__global__ void __launch_bounds__(TPB, 1) __cluster_dims__(CLUSTER, 1, 1)
fused_kernel(
    const float* __restrict__ x,    const float* __restrict__ eps,
    const float* __restrict__ ew1,  const float* __restrict__ eb1,
    const float* __restrict__ ew2,  const float* __restrict__ eb2,
    const float* __restrict__ muw,  const float* __restrict__ mub,
    const float* __restrict__ lvw,  const float* __restrict__ lvb,
    const float* __restrict__ dw1,  const float* __restrict__ db1,
    const float* __restrict__ dw2,  const float* __restrict__ db2,
    const float* __restrict__ cpw,  const float* __restrict__ cpb,
    const float* __restrict__ rw1,  const float* __restrict__ rb1,
    const float* __restrict__ rw2w, const float* __restrict__ rb2,
    const float* __restrict__ wdw,  const float* __restrict__ wdb,
    const float* __restrict__ alw,  const float* __restrict__ alb,
    float* __restrict__ out)
{
    extern __shared__ float wb[];

    const int b   = blockIdx.x;
    const int tid = threadIdx.x;

    __shared__ alignas(16) unsigned long long mbars[NSTAGES * 2];
    __shared__ float sx[784];
    __shared__ float h1[256];
    __shared__ float h2[256];
    __shared__ float muv[64];
    __shared__ float hin[92];
    __shared__ float d1[512];
    __shared__ float d2[512];
    __shared__ float r1[512];
    __shared__ float pts[52];
    __shared__ alignas(16) float red[2048];
    __shared__ float red2[512];
    __shared__ float qx[64], qy[64], wa[4];
    __shared__ alignas(16) float4 pt4[64];

    WPtrs wp; wp.ew1 = ew1; wp.ew2 = ew2; wp.muw = muw; wp.lvw = lvw;
    wp.dw1 = dw1; wp.dw2 = dw2; wp.cpw = cpw; wp.wdw = wdw; wp.alw = alw;
    wp.rw1 = rw1; wp.rw2 = rw2w;

    const uint32_t bar_base  = smem_u32(mbars);
    const uint32_t ring_base = smem_u32(wb);
    uint32_t rank;
    asm("mov.u32 %0, %%cluster_ctarank;" : "=r"(rank));

    if (tid == 0) {
        #pragma unroll
        for (int s = 0; s < NSTAGES; s++) {
            mbar_init(bar_base + s * 16, 1);
            mbar_init(bar_base + s * 16 + 8, 64);
        }
    }
    __syncthreads();
    cluster_sync_all();

    if (tid >= NGATE) {
        if (tid == NGATE) {
            for (int j = 0; j < NT; j++) produce(j, bar_base, ring_base, wp, rank);
        }
    } else {
        if (tid < NC) {
            for (int i = tid; i < 784; i += NC) sx[i] = x[b * 784 + i];
            CONS_SYNC();

            int tn = 0;
            float* ws;

            // enc1: 784->256, 13 tiles. kg=tid>>6 (8-way K), 4 cols/thread
            {
                const int kg = tid >> 6, q = (tid & 63) * 4;
                float a0 = 0, a1 = 0, a2 = 0, a3 = 0;
                for (int t = 0; t < 13; t++) {
                    TILE_BEGIN();
                    const int per = (t < 12) ? 8 : 2;
                    const int rb = kg * per;
                    #pragma unroll 8
                    for (int r = 0; r < per; r++) {
                        const float av = sx[t * 64 + rb + r];
                        const float4 w4 = *(const float4*)&ws[(rb + r) * 256 + q];
                        a0 = fmaf(av, w4.x, a0); a1 = fmaf(av, w4.y, a1);
                        a2 = fmaf(av, w4.z, a2); a3 = fmaf(av, w4.w, a3);
                    }
                    TILE_END();
                }
                *(float4*)&red[kg * 256 + q] = make_float4(a0, a1, a2, a3);
            }
            CONS_SYNC();
            if (tid < 256) {
                float s = eb1[tid];
                #pragma unroll
                for (int k = 0; k < 8; k++) s += red[k * 256 + tid];
                h1[tid] = lrelu(s);
            }
            CONS_SYNC();

            // enc2: 256->256, 4 tiles
            {
                const int kg = tid >> 6, q = (tid & 63) * 4;
                float a0 = 0, a1 = 0, a2 = 0, a3 = 0;
                for (int t = 0; t < 4; t++) {
                    TILE_BEGIN();
                    const int rb = kg * 8;
                    #pragma unroll 8
                    for (int r = 0; r < 8; r++) {
                        const float av = h1[t * 64 + rb + r];
                        const float4 w4 = *(const float4*)&ws[(rb + r) * 256 + q];
                        a0 = fmaf(av, w4.x, a0); a1 = fmaf(av, w4.y, a1);
                        a2 = fmaf(av, w4.z, a2); a3 = fmaf(av, w4.w, a3);
                    }
                    TILE_END();
                }
                *(float4*)&red[kg * 256 + q] = make_float4(a0, a1, a2, a3);
            }
            CONS_SYNC();
            if (tid < 256) {
                float s = eb2[tid];
                #pragma unroll
                for (int k = 0; k < 8; k++) s += red[k * 256 + tid];
                h2[tid] = lrelu(s);
            }
            CONS_SYNC();

            // mu: 256->64 (1 tile), 8-way K split
            {
                const int g = tid >> 6, l = tid & 63;
                TILE_BEGIN();
                float a = 0.0f;
                #pragma unroll 8
                for (int i = 0; i < 32; i++) {
                    int kl = g * 32 + i;
                    a = fmaf(h2[kl], ws[kl * 64 + l], a);
                }
                red[tid] = a;
                TILE_END();
            }
            CONS_SYNC();
            if (tid < 64) {
                float s = mub[tid];
                #pragma unroll
                for (int k = 0; k < 8; k++) s += red[k * 64 + tid];
                muv[tid] = s;
            }
            CONS_SYNC();

            // logvar: 256->64 (1 tile)
            {
                const int g = tid >> 6, l = tid & 63;
                TILE_BEGIN();
                float a = 0.0f;
                #pragma unroll 8
                for (int i = 0; i < 32; i++) {
                    int kl = g * 32 + i;
                    a = fmaf(h2[kl], ws[kl * 64 + l], a);
                }
                red[tid] = a;
                TILE_END();
            }
            CONS_SYNC();
            if (tid < 64) {
                float lvV = lvb[tid];
                #pragma unroll
                for (int k = 0; k < 8; k++) lvV += red[k * 64 + tid];
                float m = muv[tid];
                out[OUT_MU + b * 64 + tid] = m;
                out[OUT_LV + b * 64 + tid] = lvV;
                hin[tid] = m + eps[b * 64 + tid] * expf(0.5f * lvV);
            }
            CONS_SYNC();

            // dec1: 64->512, 2 tiles. kg=tid>>7 (4-way K), 4 cols/thread
            {
                const int kg = tid >> 7, q = (tid & 127) * 4;
                float a0 = 0, a1 = 0, a2 = 0, a3 = 0;
                for (int t = 0; t < 2; t++) {
                    TILE_BEGIN();
                    const int rb = kg * 8;
                    #pragma unroll 8
                    for (int r = 0; r < 8; r++) {
                        const float av = hin[t * 32 + rb + r];
                        const float4 w4 = *(const float4*)&ws[(rb + r) * 512 + q];
                        a0 = fmaf(av, w4.x, a0); a1 = fmaf(av, w4.y, a1);
                        a2 = fmaf(av, w4.z, a2); a3 = fmaf(av, w4.w, a3);
                    }
                    TILE_END();
                }
                *(float4*)&red[kg * 512 + q] = make_float4(a0, a1, a2, a3);
            }
            CONS_SYNC();
            {
                float s = db1[tid] + ((red[tid] + red[512 + tid]) + (red[1024 + tid] + red[1536 + tid]));
                d1[tid] = seluf(s);
            }
            CONS_SYNC();

            // dec2: 512->512, 16 tiles
            {
                const int kg = tid >> 7, q = (tid & 127) * 4;
                float a0 = 0, a1 = 0, a2 = 0, a3 = 0;
                for (int t = 0; t < 16; t++) {
                    TILE_BEGIN();
                    const int rb = kg * 8;
                    #pragma unroll 8
                    for (int r = 0; r < 8; r++) {
                        const float av = d1[t * 32 + rb + r];
                        const float4 w4 = *(const float4*)&ws[(rb + r) * 512 + q];
                        a0 = fmaf(av, w4.x, a0); a1 = fmaf(av, w4.y, a1);
                        a2 = fmaf(av, w4.z, a2); a3 = fmaf(av, w4.w, a3);
                    }
                    TILE_END();
                }
                *(float4*)&red[kg * 512 + q] = make_float4(a0, a1, a2, a3);
            }
            CONS_SYNC();
            {
                float s = db2[tid] + ((red[tid] + red[512 + tid]) + (red[1024 + tid] + red[1536 + tid]));
                d2[tid] = seluf(s);
            }
            CONS_SYNC();

            // coarse cp: 512->28 (1 tile), 16-way K split
            {
                const int g = tid >> 5, l = tid & 31;
                TILE_BEGIN();
                float a = 0.0f;
                if (l < 28) {
                    #pragma unroll 8
                    for (int i = 0; i < 32; i++) {
                        int kl = g * 32 + i;
                        a = fmaf(d2[kl], ws[kl * 28 + l], a);
                    }
                }
                red[tid] = a;
                TILE_END();
            }
            CONS_SYNC();
            if (tid < 28) {
                float s = cpb[tid];
                #pragma unroll
                for (int k = 0; k < 16; k++) s += red[k * 32 + tid];
                hin[64 + tid] = tanhf(s);
            }
            CONS_SYNC();

            // widths + alphas (1 fused tile)
            {
                const int pp = tid >> 8, l = tid & 255;
                TILE_BEGIN();
                float aw = fmaf(d2[l], ws[l * 2 + pp], 0.0f);
                aw = fmaf(d2[l + 256], ws[(l + 256) * 2 + pp], aw);
                float aa = fmaf(d2[l], ws[1024 + l * 2 + pp], 0.0f);
                aa = fmaf(d2[l + 256], ws[1024 + (l + 256) * 2 + pp], aa);
                red[tid] = aw; red2[tid] = aa;
                TILE_END();
            }
            CONS_SYNC();
            if (tid < 2) {
                const float* rp = &red[tid * 256];
                float s0 = 0, s1 = 0, s2 = 0, s3 = 0;
                #pragma unroll
                for (int j = 0; j < 64; j++) { s0 += rp[j]; s1 += rp[64 + j]; s2 += rp[128 + j]; s3 += rp[192 + j]; }
                float wv = sigm(wdb[tid] + ((s0 + s1) + (s2 + s3))) * 2.0f + 1.0f;
                wa[tid] = wv;
                out[OUT_W + b * 2 + tid] = wv;
            } else if (tid >= 32 && tid < 34) {
                const int pA = tid - 32;
                const float* rp = &red2[pA * 256];
                float s0 = 0, s1 = 0, s2 = 0, s3 = 0;
                #pragma unroll
                for (int j = 0; j < 64; j++) { s0 += rp[j]; s1 += rp[64 + j]; s2 += rp[128 + j]; s3 += rp[192 + j]; }
                float av = sigm(alb[pA] + ((s0 + s1) + (s2 + s3)));
                wa[2 + pA] = av;
                out[OUT_A + b * 2 + pA] = av;
            }
            CONS_SYNC();

            // refine1: 92->512, 3 tiles (32,32,28). 4-way K, 4 cols/thread
            {
                const int kg = tid >> 7, q = (tid & 127) * 4;
                float a0 = 0, a1 = 0, a2 = 0, a3 = 0;
                for (int t = 0; t < 3; t++) {
                    TILE_BEGIN();
                    const int per = (t < 2) ? 8 : 7;
                    const int rb = kg * per;
                    #pragma unroll 8
                    for (int r = 0; r < per; r++) {
                        const float av = hin[t * 32 + rb + r];
                        const float4 w4 = *(const float4*)&ws[(rb + r) * 512 + q];
                        a0 = fmaf(av, w4.x, a0); a1 = fmaf(av, w4.y, a1);
                        a2 = fmaf(av, w4.z, a2); a3 = fmaf(av, w4.w, a3);
                    }
                    TILE_END();
                }
                *(float4*)&red[kg * 512 + q] = make_float4(a0, a1, a2, a3);
            }
            CONS_SYNC();
            {
                float s = rb1[tid] + ((red[tid] + red[512 + tid]) + (red[1024 + tid] + red[1536 + tid]));
                r1[tid] = seluf(s);
            }
            CONS_SYNC();

            // refine2: 512->52 (2 tiles of 256 rows), 8-way K split
            {
                const int g = tid >> 6, l = tid & 63;
                float a = 0.0f;
                for (int t = 0; t < 2; t++) {
                    TILE_BEGIN();
                    if (l < 52) {
                        #pragma unroll 8
                        for (int i = 0; i < 32; i++) {
                            int kl = g * 32 + i;
                            a = fmaf(r1[t * 256 + kl], ws[kl * 52 + l], a);
                        }
                    }
                    TILE_END();
                }
                red[tid] = a;
            }
            CONS_SYNC();
            if (tid < 52) {
                float s = rb2[tid];
                #pragma unroll
                for (int k = 0; k < 8; k++) s += red[k * 64 + tid];
                pts[tid] = tanhf(s) * SCALEC + HALFC;
            }
            CONS_SYNC();

            // control points out + bezier sample eval
            if (tid < 64) {
                const int p = tid >> 5, rem = tid & 31;
                {
                    int s = rem >> 3, k = (rem >> 1) & 3, d = rem & 1;
                    out[OUT_CP + b * 64 + tid] = pts[p * 26 + (3 * s + k) * 2 + d];
                }
                const int ss = rem >> 3, ti = rem & 7;
                float t  = (float)ti / 7.0f;
                float mt = 1.0f - t;
                float b0 = mt * mt * mt;
                float b1 = 3.0f * mt * mt * t;
                float b2 = 3.0f * mt * t * t;
                float b3 = t * t * t;
                int base = p * 26 + (3 * ss) * 2;
                float X = b0 * pts[base + 0] + b1 * pts[base + 2] + b2 * pts[base + 4] + b3 * pts[base + 6];
                float Y = b0 * pts[base + 1] + b1 * pts[base + 3] + b2 * pts[base + 5] + b3 * pts[base + 7];
                qx[tid] = X; qy[tid] = Y;
            }
            CONS_SYNC();
            if (tid < 64) {
                const int p = tid >> 5, m = tid & 31;
                float X = qx[tid], Y = qy[tid];
                float y1 = qy[p * 32 + ((m + 1) & 31)];
                float si = __fdiv_rn(1.0f, (y1 - Y) + 1e-8f);
                pt4[tid] = make_float4(X, Y, X * X + Y * Y, si);
            }
        }

        GATE_SYNC();

        // rasterizer: 1 pixel/thread
        if (tid < 784) {
            const int px = tid;
            const int pi = px / 28, pj = px - pi * 28;
            float syv[4], sxv[4], nxv[4], nyv[4], ssn[4], val[4];
            #pragma unroll
            for (int s = 0; s < 4; s++) {
                syv[s] = (float)pi + (0.25f + 0.5f * (float)(s >> 1));
                sxv[s] = (float)pj + (0.25f + 0.5f * (float)(s & 1));
                nxv[s] = -2.0f * sxv[s];
                nyv[s] = -2.0f * syv[s];
                ssn[s] = sxv[s] * sxv[s] + syv[s] * syv[s];
                val[s] = 1.0f;
            }
            #pragma unroll
            for (int p = 0; p < 2; p++) {
                const int base = p * 32;
                float mind2[4]; int nc[4]; bool c0[4];
                float4 e = pt4[base];
                #pragma unroll
                for (int s = 0; s < 4; s++) {
                    mind2[s] = 3.402823e38f; nc[s] = 0; c0[s] = e.y > syv[s];
                }
                #pragma unroll 8
                for (int m = 0; m < 32; m++) {
                    const float4 e1 = pt4[base + ((m + 1) & 31)];
                    const float dx = e1.x - e.x;
                    #pragma unroll
                    for (int s = 0; s < 4; s++) {
                        float v = fmaf(nxv[s], e.x, fmaf(nyv[s], e.y, e.z + ssn[s]));
                        mind2[s] = fminf(mind2[s], v);
                        const bool c1 = e1.y > syv[s];
                        const float xint = fmaf((syv[s] - e.y) * e.w, dx, e.x);
                        nc[s] += (int)((c0[s] != c1) && (sxv[s] < xint));
                        c0[s] = c1;
                    }
                    e = e1;
                }
                const float sw  = fmaf(wa[p], 0.5f, 0.5f);   // hoisted out of subsample loop
                const float al2 = wa[2 + p];
                #pragma unroll
                for (int s = 0; s < 4; s++) {
                    const float dist   = sqrtf(fmaxf(mind2[s], 0.0f));
                    const float stroke = fminf(fmaxf(sw - dist, 0.0f), 1.0f);
                    const float cov    = fmaxf((float)(nc[s] & 1), stroke);
                    val[s] *= 1.0f - al2 * cov;
                }
            }
            const float acc = (val[0] + val[1]) + (val[2] + val[3]);
            out[OUT_R + b * 784 + px] = 1.0f - 0.25f * acc;
        }
    }

    cluster_sync_all();
}

extern "C" void kernel_launch(void* const* d_in, const int* in_sizes, int n_in,
                              void* d_out, int out_size)
{
    const float* x    = (const float*)d_in[0];
    const float* eps  = (const float*)d_in[1];
    const float* ew1  = (const float*)d_in[2];
    const float* eb1  = (const float*)d_in[3];
    const float* ew2  = (const float*)d_in[4];
    const float* eb2  = (const float*)d_in[5];
    const float* muw  = (const float*)d_in[6];
    const float* mub  = (const float*)d_in[7];
    const float* lvw  = (const float*)d_in[8];
    const float* lvb  = (const float*)d_in[9];
    const float* dw1  = (const float*)d_in[10];
    const float* db1  = (const float*)d_in[11];
    const float* dw2  = (const float*)d_in[12];
    const float* db2  = (const float*)d_in[13];
    const float* cpw  = (const float*)d_in[14];
    const float* cpb  = (const float*)d_in[15];
    const float* rw1  = (const float*)d_in[16];
    const float* rb1  = (const float*)d_in[17];
    const float* rw2  = (const float*)d_in[18];
    const float* rb2  = (const float*)d_in[19];
    const float* wdw  = (const float*)d_in[20];
    const float* wdb  = (const float*)d_in[21];
    const float* alw  = (const float*)d_in[22];
    const float* alb  = (const float*)d_in[23];
    float* out = (float*)d_out;

    const int dyn = NSTAGES * STAGE_BYTES;
    cudaFuncSetAttribute(fused_kernel, cudaFuncAttributeMaxDynamicSharedMemorySize, dyn);
    fused_kernel<<<BATCH, TPB, dyn>>>(x, eps, ew1, eb1, ew2, eb2, muw, mub, lvw, lvb,
                                      dw1, db1, dw2, db2, cpw, cpb, rw1, rb1, rw2, rb2,
                                      wdw, wdb, alw, alb, out);
}